// round 1
// baseline (speedup 1.0000x reference)
#include <cuda_runtime.h>

// Conv_44220983280108: 3x3 SAME conv + ReLU
//   x:   [224, 224, 128] fp32
//   W:   [256, 1152] fp32, flat index = kh*3*128 + kw*128 + c
//   out: [224, 224, 256] fp32
//
// Implicit-GEMM, register-blocked. Block tile: 8x16 pixels x 128 couts.
// Thread tile: 8 pixels x 8 couts (64 accumulators). 256 threads/block.

#define IH 224
#define IW 224
#define CI 128
#define CO 256

#define TH 8     // output rows per block
#define TW 16    // output cols per block
#define TN 128   // couts per block
#define CH 16    // channel chunk per smem stage
#define BPAD 4   // Bs pitch padding (bank-conflict break)

__global__ __launch_bounds__(256, 2)
void conv3x3_relu_kernel(const float* __restrict__ x,
                         const float* __restrict__ Wt,
                         float* __restrict__ out) {
    __shared__ float As[TH + 2][TW + 2][CH];      // 10*18*16 = 11.52 KB
    __shared__ float Bs[CH][TN + BPAD];           // 16*132   =  8.45 KB

    const int tid = threadIdx.x;
    const int tx  = tid & 15;        // 0..15 -> cout group
    const int ty  = tid >> 4;        // 0..15 -> pixel group

    const int oh0 = blockIdx.y * TH;
    const int ow0 = blockIdx.x * TW;
    const int co0 = blockIdx.z * TN;

    const int r  = ty >> 1;          // local output row (0..7)
    const int cb = (ty & 1) * 8;     // local output col base (0 or 8)
    const int n0 = tx * 8;           // local cout base

    float acc[8][8];
#pragma unroll
    for (int i = 0; i < 8; ++i)
#pragma unroll
        for (int j = 0; j < 8; ++j) acc[i][j] = 0.f;

    for (int c0 = 0; c0 < CI; c0 += CH) {
        __syncthreads();  // protect As from previous iteration's readers

        // ---- Load input halo tile (TH+2)x(TW+2)xCH as float4 over channels.
        // 10*18*4 = 720 float4 loads, 256 threads.
        for (int idx = tid; idx < (TH + 2) * (TW + 2) * (CH / 4); idx += 256) {
            const int c4  = idx & 3;
            const int col = (idx >> 2) % (TW + 2);
            const int row = idx / (4 * (TW + 2));
            const int ih  = oh0 - 1 + row;
            const int iw  = ow0 - 1 + col;
            float4 v = make_float4(0.f, 0.f, 0.f, 0.f);
            if ((unsigned)ih < IH && (unsigned)iw < IW) {
                v = *reinterpret_cast<const float4*>(
                        &x[((ih * IW + iw) * CI) + c0 + c4 * 4]);
            }
            *reinterpret_cast<float4*>(&As[row][col][c4 * 4]) = v;
        }

        for (int kk = 0; kk < 9; ++kk) {   // (kh, kw) taps
            const int kh = kk / 3;
            const int kw = kk - kh * 3;

            __syncthreads();  // As ready (kk==0); Bs readers done (kk>0)

            // ---- Load weight tile CH x TN (transposed into Bs[c][cout]).
            // 2048 floats = 512 float4 loads.
            const int wbase = kk * CI + c0;
            for (int t = tid; t < (CH * TN) / 4; t += 256) {
                const int c4 = t & 3;
                const int co = t >> 2;
                float4 v = *reinterpret_cast<const float4*>(
                        &Wt[(size_t)(co0 + co) * (CI * 9) + wbase + c4 * 4]);
                Bs[c4 * 4 + 0][co] = v.x;
                Bs[c4 * 4 + 1][co] = v.y;
                Bs[c4 * 4 + 2][co] = v.z;
                Bs[c4 * 4 + 3][co] = v.w;
            }
            __syncthreads();

            // ---- 16 K-steps of 8x8 outer product per thread.
#pragma unroll
            for (int c = 0; c < CH; ++c) {
                float bb[8];
                *reinterpret_cast<float4*>(&bb[0]) =
                    *reinterpret_cast<const float4*>(&Bs[c][n0]);
                *reinterpret_cast<float4*>(&bb[4]) =
                    *reinterpret_cast<const float4*>(&Bs[c][n0 + 4]);
                float aa[8];
#pragma unroll
                for (int i = 0; i < 8; ++i)
                    aa[i] = As[r + kh][cb + i + kw][c];
#pragma unroll
                for (int i = 0; i < 8; ++i)
#pragma unroll
                    for (int j = 0; j < 8; ++j)
                        acc[i][j] = fmaf(aa[i], bb[j], acc[i][j]);
            }
        }
    }

    // ---- Epilogue: ReLU + vectorized store. All 8 pixels share row r.
    const int oh = oh0 + r;
#pragma unroll
    for (int i = 0; i < 8; ++i) {
        const int ow = ow0 + cb + i;
        float* p = &out[((size_t)(oh * IW + ow) * CO) + co0 + n0];
        float4 v0, v1;
        v0.x = fmaxf(acc[i][0], 0.f); v0.y = fmaxf(acc[i][1], 0.f);
        v0.z = fmaxf(acc[i][2], 0.f); v0.w = fmaxf(acc[i][3], 0.f);
        v1.x = fmaxf(acc[i][4], 0.f); v1.y = fmaxf(acc[i][5], 0.f);
        v1.z = fmaxf(acc[i][6], 0.f); v1.w = fmaxf(acc[i][7], 0.f);
        *reinterpret_cast<float4*>(p)     = v0;
        *reinterpret_cast<float4*>(p + 4) = v1;
    }
}

extern "C" void kernel_launch(void* const* d_in, const int* in_sizes, int n_in,
                              void* d_out, int out_size) {
    const float* x  = (const float*)d_in[0];   // 224*224*128
    const float* Wt = (const float*)d_in[1];   // 256*1152
    float* out      = (float*)d_out;           // 224*224*256

    dim3 grid(IW / TW, IH / TH, CO / TN);      // 14 x 28 x 2
    conv3x3_relu_kernel<<<grid, 256>>>(x, Wt, out);
}

// round 4
// speedup vs baseline: 2.4717x; 2.4717x over previous
#include <cuda_runtime.h>
#include <cuda_bf16.h>
#include <cstdint>

// Conv_44220983280108: 3x3 SAME conv + ReLU.
//   x: [224,224,128] f32, W: [256,1152] f32 (flat = kh*384 + kw*128 + c),
//   out: [224,224,256] f32.
// Implicit GEMM D[50176,256] = im2col(x)[50176,1152] * W^T via
// mma.sync.m16n8k16 bf16 (sm_80+ path; tcgen05 unavailable: harness PTX
// target is sm_100, not sm_100a). fp32 accuracy via bf16 hi/lo split,
// 3 passes: Ah*Bh + Ah*Bl + Al*Bh.
// R4 fix: B fragment uses non-trans ldmatrix.x2 (B staged [n][k] row-major).

#define IH 224
#define IW 224
#define CI 128
#define CO 256
#define NPIX (IH * IW)      // 50176
#define MT 128              // pixels per CTA
#define NT 128              // couts per CTA
#define KS 64               // K per stage (one tap ch-half)
#define NSTAGE 18           // 9 taps * 2 halves
#define PADK 72             // halves per smem row (144 B pitch)
#define ROWB (PADK * 2)     // 144
#define ARR (128 * ROWB)    // 18432 B per tile array
#define STAGEB (4 * ARR)    // Ah, Al, Bh, Bl
#define SMEM_TOTAL (2 * STAGEB)  // 147456 B double-buffered

// ---- device scratch (no runtime allocation allowed) ----
__device__ __nv_bfloat16 g_xhi[NPIX * CI];
__device__ __nv_bfloat16 g_xlo[NPIX * CI];
__device__ __nv_bfloat16 g_whi[CO * CI * 9];
__device__ __nv_bfloat16 g_wlo[CO * CI * 9];

// ======================= helpers =======================
__device__ __forceinline__ uint32_t smem_u32(const void* p) {
    uint32_t a;
    asm("{ .reg .u64 t; cvta.to.shared.u64 t, %1; cvt.u32.u64 %0, t; }"
        : "=r"(a) : "l"(p));
    return a;
}
__device__ __forceinline__ void cp16(uint32_t dst, const void* src, int srcsize) {
    asm volatile("cp.async.cg.shared.global [%0], [%1], 16, %2;"
                 :: "r"(dst), "l"(src), "r"(srcsize) : "memory");
}
#define CP_COMMIT() asm volatile("cp.async.commit_group;" ::: "memory")
#define CP_WAIT(n)  asm volatile("cp.async.wait_group %0;" :: "n"(n) : "memory")

__device__ __forceinline__ void ldmx4(uint32_t* r, uint32_t addr) {
    asm volatile("ldmatrix.sync.aligned.m8n8.x4.shared.b16 {%0,%1,%2,%3}, [%4];"
                 : "=r"(r[0]), "=r"(r[1]), "=r"(r[2]), "=r"(r[3]) : "r"(addr));
}
__device__ __forceinline__ void ldmx2(uint32_t* r, uint32_t addr) {
    asm volatile("ldmatrix.sync.aligned.m8n8.x2.shared.b16 {%0,%1}, [%2];"
                 : "=r"(r[0]), "=r"(r[1]) : "r"(addr));
}
__device__ __forceinline__ void mma_bf16(float* d, const uint32_t* a,
                                         const uint32_t* b) {
    asm volatile(
        "mma.sync.aligned.m16n8k16.row.col.f32.bf16.bf16.f32 "
        "{%0,%1,%2,%3}, {%4,%5,%6,%7}, {%8,%9}, {%0,%1,%2,%3};"
        : "+f"(d[0]), "+f"(d[1]), "+f"(d[2]), "+f"(d[3])
        : "r"(a[0]), "r"(a[1]), "r"(a[2]), "r"(a[3]), "r"(b[0]), "r"(b[1]));
}

// ======================= prep kernels =======================
__global__ void split_x_kernel(const float* __restrict__ x) {
    int i = blockIdx.x * blockDim.x + threadIdx.x;
    if (i >= NPIX * CI) return;
    float v = x[i];
    __nv_bfloat16 hi = __float2bfloat16(v);
    g_xhi[i] = hi;
    g_xlo[i] = __float2bfloat16(v - __bfloat162float(hi));
}
__global__ void split_w_kernel(const float* __restrict__ W) {
    int i = blockIdx.x * blockDim.x + threadIdx.x;
    if (i >= CO * CI * 9) return;
    float v = W[i];
    __nv_bfloat16 hi = __float2bfloat16(v);
    g_whi[i] = hi;
    g_wlo[i] = __float2bfloat16(v - __bfloat162float(hi));
}

// ======================= main kernel =======================
__device__ __forceinline__ void issue_stage(uint32_t sb, int buf, int s,
                                            int mbase, int ntile, int tid) {
    const int tap = s >> 1;
    const int q = s & 1;
    const int kh = tap / 3, kw = tap - kh * 3;
    const uint32_t base = sb + (uint32_t)buf * STAGEB;
    const __nv_bfloat16* xs[2] = {g_xhi, g_xlo};
    const __nv_bfloat16* ws[2] = {g_whi, g_wlo};

#pragma unroll
    for (int it = 0; it < 8; ++it) {
        const int i = tid + it * 512;           // 0..4095
        const int which = i >> 11;              // 0 = A, 1 = B
        const int ver = (i >> 10) & 1;          // 0 = hi, 1 = lo
        const int rem = i & 1023;
        const int r = rem >> 3;                 // row (pixel or cout)
        const int ch = rem & 7;                 // 16B chunk within K=64
        const uint32_t dst = base + (uint32_t)((which * 2 + ver) * ARR
                                               + r * ROWB + ch * 16);
        if (which == 0) {
            const int p = mbase + r;
            const int h = p / IW;
            const int w = p - h * IW;
            const int hs = h + kh - 1, ws_ = w + kw - 1;
            const bool ok = ((unsigned)hs < IH) & ((unsigned)ws_ < IW);
            const int si = ok ? ((hs * IW + ws_) * CI + q * KS + ch * 8) : 0;
            cp16(dst, xs[ver] + si, ok ? 16 : 0);
        } else {
            const int si = (ntile * NT + r) * (CI * 9) + tap * CI + q * KS + ch * 8;
            cp16(dst, ws[ver] + si, 16);
        }
    }
    CP_COMMIT();
}

__global__ void __launch_bounds__(512, 1)
conv_mma_kernel(float* __restrict__ out) {
    extern __shared__ char smem[];
    const uint32_t sb = smem_u32(smem);

    const int tid = threadIdx.x;
    const int lane = tid & 31;
    const int wid = tid >> 5;
    const int wm = wid & 3;        // warp M group (4)
    const int wn = wid >> 2;       // warp N group (4)

    const int mtile = blockIdx.x;  // 0..391
    const int ntile = blockIdx.y;  // 0..1
    const int mbase = mtile * MT;

    float acc[2][4][4];
#pragma unroll
    for (int mt = 0; mt < 2; ++mt)
#pragma unroll
        for (int nt = 0; nt < 4; ++nt)
#pragma unroll
            for (int j = 0; j < 4; ++j) acc[mt][nt][j] = 0.f;

    // per-lane ldmatrix base offsets (bytes, within one array)
    uint32_t aOff[2], bOff[4];
#pragma unroll
    for (int mt = 0; mt < 2; ++mt) {
        const int row = wm * 32 + mt * 16 + ((lane >> 3) & 1) * 8 + (lane & 7);
        aOff[mt] = (uint32_t)(row * ROWB + (lane >> 4) * 16);
    }
#pragma unroll
    for (int nt = 0; nt < 4; ++nt) {
        // non-trans x2: lanes 0-7 -> n rows at k0..7, lanes 8-15 -> +16B (k8..15)
        const int row = wn * 32 + nt * 8 + (lane & 7);
        bOff[nt] = (uint32_t)(row * ROWB + ((lane >> 3) & 1) * 16);
    }

    issue_stage(sb, 0, 0, mbase, ntile, tid);

    for (int s = 0; s < NSTAGE; ++s) {
        if (s + 1 < NSTAGE) {
            issue_stage(sb, (s + 1) & 1, s + 1, mbase, ntile, tid);
            CP_WAIT(1);
        } else {
            CP_WAIT(0);
        }
        __syncthreads();

        const uint32_t base = sb + (uint32_t)(s & 1) * STAGEB;
        const uint32_t Ah = base, Al = base + ARR;
        const uint32_t Bh = base + 2 * ARR, Bl = base + 3 * ARR;

#pragma unroll
        for (int kk = 0; kk < 4; ++kk) {
            const uint32_t ko = (uint32_t)kk * 32;
            uint32_t ah[2][4], al[2][4], bh[4][2], bl[4][2];
#pragma unroll
            for (int mt = 0; mt < 2; ++mt) {
                ldmx4(ah[mt], Ah + aOff[mt] + ko);
                ldmx4(al[mt], Al + aOff[mt] + ko);
            }
#pragma unroll
            for (int nt = 0; nt < 4; ++nt) {
                ldmx2(bh[nt], Bh + bOff[nt] + ko);
                ldmx2(bl[nt], Bl + bOff[nt] + ko);
            }
#pragma unroll
            for (int mt = 0; mt < 2; ++mt)
#pragma unroll
                for (int nt = 0; nt < 4; ++nt) {
                    mma_bf16(acc[mt][nt], ah[mt], bh[nt]);
                    mma_bf16(acc[mt][nt], ah[mt], bl[nt]);
                    mma_bf16(acc[mt][nt], al[mt], bh[nt]);
                }
        }
        __syncthreads();
    }

    // ---- epilogue: ReLU + float2 stores (full 32B sectors per quad) ----
#pragma unroll
    for (int mt = 0; mt < 2; ++mt) {
        const int m0 = mbase + wm * 32 + mt * 16 + (lane >> 2);
#pragma unroll
        for (int nt = 0; nt < 4; ++nt) {
            const int col = ntile * NT + wn * 32 + nt * 8 + (lane & 3) * 2;
            float2 v0, v1;
            v0.x = fmaxf(acc[mt][nt][0], 0.f);
            v0.y = fmaxf(acc[mt][nt][1], 0.f);
            v1.x = fmaxf(acc[mt][nt][2], 0.f);
            v1.y = fmaxf(acc[mt][nt][3], 0.f);
            *(float2*)(out + (size_t)m0 * CO + col) = v0;
            *(float2*)(out + (size_t)(m0 + 8) * CO + col) = v1;
        }
    }
}

// ======================= launch =======================
extern "C" void kernel_launch(void* const* d_in, const int* in_sizes, int n_in,
                              void* d_out, int out_size) {
    const float* x = (const float*)d_in[0];   // 224*224*128
    const float* W = (const float*)d_in[1];   // 256*1152
    float* out = (float*)d_out;

    cudaFuncSetAttribute(conv_mma_kernel,
                         cudaFuncAttributeMaxDynamicSharedMemorySize, SMEM_TOTAL);

    split_x_kernel<<<(NPIX * CI + 255) / 256, 256>>>(x);
    split_w_kernel<<<(CO * CI * 9 + 255) / 256, 256>>>(W);
    conv_mma_kernel<<<dim3(NPIX / MT, CO / NT), 512, SMEM_TOTAL>>>(out);
}